// round 16
// baseline (speedup 1.0000x reference)
#include <cuda_runtime.h>

#define TPB     128
#define NBLOCKS 1184       // 148 SMs x 8 CTAs/SM

__device__ __forceinline__ float tanha(float x) {
    float y;
    asm("tanh.approx.f32 %0, %1;" : "=f"(y) : "f"(x));
    return y;
}

// SMEM float4 layout (28 entries):
//  [0..7]   L1 pack j: {W1[0][j], W1[1][j], W1[2][j], b1[j]}
//  [8..15]  L2 pack: [8+2j]={W2[0..3][j]}, [9+2j]={W2[4..7][j]}  (j=0..3)
//  [24]     {b2[0..3]}
//  [25]     {W3[0..3]}
//  [26]     {b3, wq, 0, 0}
__global__ void __launch_bounds__(TPB, 8) qnn_kernel(
    const float4* __restrict__ in,   // 2 rows per float4
    float2*       __restrict__ out,  // 2 outputs per float2
    int npairs, int nrows,
    const float* __restrict__ W1, const float* __restrict__ b1,
    const float* __restrict__ W2, const float* __restrict__ b2,
    const float* __restrict__ W3, const float* __restrict__ b3,
    const float* __restrict__ w,
    const float* __restrict__ in_scalar, float* __restrict__ out_scalar)
{
    __shared__ float4 sw4[28];
    float* swf = (float*)sw4;

    {
        const int i = threadIdx.x;
        if (i < 32) {                       // L1 pack
            const int j = i >> 2, k = i & 3;
            swf[j * 4 + k] = (k < 3) ? W1[k * 8 + j] : b1[j];
        } else if (i < 64) {                // W2 transposed pack
            const int idx = i - 32, j = idx >> 3, ii = idx & 7;
            swf[32 + j * 8 + ii] = W2[ii * 4 + j];
        } else if (i < 68)  swf[96  + (i - 64)] = b2[i - 64];
        else if (i < 72)    swf[100 + (i - 68)] = W3[i - 68];
        else if (i == 72)   swf[104] = b3[0];
        else if (i == 73)   swf[105] = w[0];
        else if (i < 80)    swf[106 + (i - 74) % 2] = 0.0f;  // pad
    }
    __syncthreads();

    // loop-invariant scalars -> registers (one LDS.128 each, once)
    const float4 vb2 = sw4[24];
    const float4 vw3 = sw4[25];
    const float4 vt  = sw4[26];
    const float rb2[4] = {vb2.x, vb2.y, vb2.z, vb2.w};
    const float rw3[4] = {vw3.x, vw3.y, vw3.z, vw3.w};
    const float rb3 = vt.x, wq = vt.y;

    const int t      = blockIdx.x * TPB + threadIdx.x;
    const int stride = NBLOCKS * TPB;

    for (int p = t; p < npairs; p += stride) {
        const float4 v = __ldg(in + p);

        const float qa = __sinf(v.x) * __sinf(v.y + wq);
        const float qb = __sinf(v.z) * __sinf(v.w + wq);

        // layer 1: one LDS.128 per neuron, both rows
        float h1a[8], h1b[8];
#pragma unroll
        for (int j = 0; j < 8; ++j) {
            const float4 Wj = sw4[j];
            float a = fmaf(Wj.x, v.x, Wj.w);
            a = fmaf(Wj.y, v.y, a);
            a = fmaf(Wj.z, qa, a);
            float b = fmaf(Wj.x, v.z, Wj.w);
            b = fmaf(Wj.y, v.w, b);
            b = fmaf(Wj.z, qb, b);
            h1a[j] = tanha(a);
            h1b[j] = tanha(b);
        }

        // layer 2: two LDS.128 per neuron, both rows
        float h2a[4], h2b[4];
#pragma unroll
        for (int j = 0; j < 4; ++j) {
            const float4 A = sw4[8 + 2 * j];
            const float4 B = sw4[9 + 2 * j];
            float a = rb2[j], b = rb2[j];
            a = fmaf(h1a[0], A.x, a);  b = fmaf(h1b[0], A.x, b);
            a = fmaf(h1a[1], A.y, a);  b = fmaf(h1b[1], A.y, b);
            a = fmaf(h1a[2], A.z, a);  b = fmaf(h1b[2], A.z, b);
            a = fmaf(h1a[3], A.w, a);  b = fmaf(h1b[3], A.w, b);
            a = fmaf(h1a[4], B.x, a);  b = fmaf(h1b[4], B.x, b);
            a = fmaf(h1a[5], B.y, a);  b = fmaf(h1b[5], B.y, b);
            a = fmaf(h1a[6], B.z, a);  b = fmaf(h1b[6], B.z, b);
            a = fmaf(h1a[7], B.w, a);  b = fmaf(h1b[7], B.w, b);
            h2a[j] = tanha(a);
            h2b[j] = tanha(b);
        }

        // layer 3 (weights in registers)
        float oa = rb3, ob = rb3;
#pragma unroll
        for (int j = 0; j < 4; ++j) {
            oa = fmaf(h2a[j], rw3[j], oa);
            ob = fmaf(h2b[j], rw3[j], ob);
        }
        out[p] = make_float2(oa, ob);
    }

    // odd trailing row
    if ((nrows & 1) && t == 0) {
        const float x0 = __ldg(in_scalar + (nrows - 1) * 2);
        const float x1 = __ldg(in_scalar + (nrows - 1) * 2 + 1);
        const float q = __sinf(x0) * __sinf(x1 + wq);
        float h1[8];
#pragma unroll
        for (int j = 0; j < 8; ++j) {
            const float4 Wj = sw4[j];
            float a = fmaf(Wj.x, x0, Wj.w);
            a = fmaf(Wj.y, x1, a);
            a = fmaf(Wj.z, q, a);
            h1[j] = tanha(a);
        }
        float o = rb3;
#pragma unroll
        for (int j = 0; j < 4; ++j) {
            const float4 A = sw4[8 + 2 * j];
            const float4 B = sw4[9 + 2 * j];
            float a = rb2[j];
            a = fmaf(h1[0], A.x, a); a = fmaf(h1[1], A.y, a);
            a = fmaf(h1[2], A.z, a); a = fmaf(h1[3], A.w, a);
            a = fmaf(h1[4], B.x, a); a = fmaf(h1[5], B.y, a);
            a = fmaf(h1[6], B.z, a); a = fmaf(h1[7], B.w, a);
            o = fmaf(tanha(a), rw3[j], o);
        }
        out_scalar[nrows - 1] = o;
    }
}

extern "C" void kernel_launch(void* const* d_in, const int* in_sizes, int n_in,
                              void* d_out, int out_size)
{
    const float* in = (const float*)d_in[0];
    const int nrows  = in_sizes[0] / 2;
    const int npairs = nrows / 2;

    qnn_kernel<<<NBLOCKS, TPB>>>(
        (const float4*)in, (float2*)d_out,
        npairs, nrows,
        (const float*)d_in[1], (const float*)d_in[2],
        (const float*)d_in[3], (const float*)d_in[4],
        (const float*)d_in[5], (const float*)d_in[6],
        (const float*)d_in[7],
        in, (float*)d_out);
}